// round 12
// baseline (speedup 1.0000x reference)
#include <cuda_runtime.h>
#include <cuda_bf16.h>
#include <cstdint>

// ---------------- problem constants ----------------
#define B_DIM   2
#define T_DIM   2048
#define DMODEL  1024
#define NHEAD   16
#define DKH     64
#define M_DIM   (B_DIM * T_DIM)      // 4096
#define KDIM    DMODEL

// ---------------- scratch (device globals, no allocs) ----------------
__device__ __nv_bfloat16 g_xhi[M_DIM * DMODEL], g_xlo[M_DIM * DMODEL];
__device__ __nv_bfloat16 g_whi[4 * DMODEL * DMODEL], g_wlo[4 * DMODEL * DMODEL];
__device__ __nv_bfloat16 g_qhi[M_DIM * DMODEL], g_qlo[M_DIM * DMODEL];   // [B,H,T,dk]
__device__ __nv_bfloat16 g_khi[M_DIM * DMODEL], g_klo[M_DIM * DMODEL];   // [B,H,T,dk]
__device__ __nv_bfloat16 g_vhi[M_DIM * DMODEL], g_vlo[M_DIM * DMODEL];   // [B,H,dk,T]
__device__ __nv_bfloat16 g_ahi[M_DIM * DMODEL], g_alo[M_DIM * DMODEL];   // [B,T,D]

// ---------------- helpers ----------------
__device__ __forceinline__ unsigned short bf2u(__nv_bfloat16 h) {
    return *reinterpret_cast<unsigned short*>(&h);
}

__device__ __forceinline__ void split2(float a, float b, uint32_t& hi, uint32_t& lo) {
    __nv_bfloat16 ha = __float2bfloat16_rn(a), hb = __float2bfloat16_rn(b);
    float ra = a - __bfloat162float(ha), rb = b - __bfloat162float(hb);
    __nv_bfloat16 la = __float2bfloat16_rn(ra), lb = __float2bfloat16_rn(rb);
    hi = ((uint32_t)bf2u(hb) << 16) | (uint32_t)bf2u(ha);
    lo = ((uint32_t)bf2u(lb) << 16) | (uint32_t)bf2u(la);
}

__device__ __forceinline__ float fexp(float x) {
    float y = x * 1.4426950408889634f;
    y = fmaxf(y, -120.0f);
    float n = floorf(y);
    float f = y - n;
    float p = 1.5403530393381606e-4f;
    p = fmaf(p, f, 1.3333558146428443e-3f);
    p = fmaf(p, f, 9.6181291076284771e-3f);
    p = fmaf(p, f, 5.5504108664821580e-2f);
    p = fmaf(p, f, 2.4022650695910071e-1f);
    p = fmaf(p, f, 6.9314718055994531e-1f);
    p = fmaf(p, f, 1.0f);
    float r = __int_as_float(((int)n + 127) << 23);
    return p * r;
}

__device__ __forceinline__ void mma_bf16(float* c, const uint32_t* a, uint32_t b0, uint32_t b1) {
    asm volatile(
        "mma.sync.aligned.m16n8k16.row.col.f32.bf16.bf16.f32 "
        "{%0,%1,%2,%3}, {%4,%5,%6,%7}, {%8,%9}, {%0,%1,%2,%3};"
        : "+f"(c[0]), "+f"(c[1]), "+f"(c[2]), "+f"(c[3])
        : "r"(a[0]), "r"(a[1]), "r"(a[2]), "r"(a[3]), "r"(b0), "r"(b1));
}

__device__ __forceinline__ void cp16(void* dst, const void* src) {
    uint32_t d = (uint32_t)__cvta_generic_to_shared(dst);
    asm volatile("cp.async.cg.shared.global [%0], [%1], 16;" :: "r"(d), "l"(src));
}
#define CP_COMMIT()  asm volatile("cp.async.commit_group;")
#define CP_WAIT(N)   asm volatile("cp.async.wait_group %0;" :: "n"(N))

// ---------------- fused bf16 split kernel (x + 4 weights in one launch) ----------------
__global__ void fused_split_kernel(
    const float* __restrict__ x,
    const float* __restrict__ Wq, const float* __restrict__ Wk,
    const float* __restrict__ Wv, const float* __restrict__ Wo,
    __nv_bfloat16* __restrict__ xhi, __nv_bfloat16* __restrict__ xlo,
    __nv_bfloat16* __restrict__ whi, __nv_bfloat16* __restrict__ wlo)
{
    const int WN = DMODEL * DMODEL;
    const int y = blockIdx.y;
    const float* src;
    __nv_bfloat16 *hi, *lo;
    int n;
    if (y == 0) { src = x; hi = xhi; lo = xlo; n = M_DIM * DMODEL; }
    else {
        const float* ws[4] = {Wq, Wk, Wv, Wo};
        src = ws[y - 1];
        hi = whi + (size_t)(y - 1) * WN;
        lo = wlo + (size_t)(y - 1) * WN;
        n = WN;
    }
    int i = (blockIdx.x * blockDim.x + threadIdx.x) * 4;
    if (i < n) {
        float4 v = *(const float4*)(src + i);
        uint32_t h0, l0, h1, l1;
        split2(v.x, v.y, h0, l0);
        split2(v.z, v.w, h1, l1);
        *(uint2*)(hi + i) = make_uint2(h0, h1);
        *(uint2*)(lo + i) = make_uint2(l0, l1);
    }
}

// ---------------- projection GEMM body (bf16x3, mma.sync) ----------------
// C[M,N] = A[M,K] * W[N,K]^T + bias, tile 128x128, BK=32, 256 thr, warp tile 64x32.
// MODE 0: fp32 flat [M,DMODEL];  MODE 1: bf16 hi/lo [B,H,T,dk];  MODE 2: bf16 hi/lo [B,H,dk,T]
#define PJ_TB   (128 * 40)
#define PJ_SMEM (4 * 2 * PJ_TB * 2)

template <int MODE>
__device__ __forceinline__ void proj_body(
    const __nv_bfloat16* __restrict__ Ahi, const __nv_bfloat16* __restrict__ Alo,
    const __nv_bfloat16* __restrict__ Bhi, const __nv_bfloat16* __restrict__ Blo,
    const float* __restrict__ bias,
    float* __restrict__ outF,
    __nv_bfloat16* __restrict__ outHi, __nv_bfloat16* __restrict__ outLo)
{
    extern __shared__ __align__(16) unsigned char smem_raw[];
    __nv_bfloat16* sA_hi = (__nv_bfloat16*)smem_raw;
    __nv_bfloat16* sA_lo = sA_hi + 2 * PJ_TB;
    __nv_bfloat16* sB_hi = sA_lo + 2 * PJ_TB;
    __nv_bfloat16* sB_lo = sB_hi + 2 * PJ_TB;

    const int tid = threadIdx.x;
    const int lane = tid & 31, wid = tid >> 5;
    const int wm = wid >> 2, wn = wid & 3;      // 2 x 4 warps
    const int m0 = blockIdx.y * 128, n0 = blockIdx.x * 128;
    const int g = lane >> 2;
    const int ke = (lane & 3);                  // u32 column unit within k16

    const int lrow = tid >> 2;                  // 0..63
    const int lch  = (tid & 3) * 8;             // elem offset of 16B chunk

    float acc[4][4][4];
#pragma unroll
    for (int a = 0; a < 4; a++)
#pragma unroll
        for (int b = 0; b < 4; b++)
#pragma unroll
            for (int c = 0; c < 4; c++) acc[a][b][c] = 0.0f;

    auto load_stage = [&](int s, int buf) {
        int k0 = s * 32;
        const __nv_bfloat16* ga_h = Ahi + (size_t)m0 * KDIM + k0;
        const __nv_bfloat16* ga_l = Alo + (size_t)m0 * KDIM + k0;
        const __nv_bfloat16* gb_h = Bhi + (size_t)n0 * KDIM + k0;
        const __nv_bfloat16* gb_l = Blo + (size_t)n0 * KDIM + k0;
#pragma unroll
        for (int i = 0; i < 2; i++) {
            int r = lrow + i * 64;
            int se = r * 40 + lch;
            size_t ge = (size_t)r * KDIM + lch;
            cp16(sA_hi + buf * PJ_TB + se, ga_h + ge);
            cp16(sA_lo + buf * PJ_TB + se, ga_l + ge);
            cp16(sB_hi + buf * PJ_TB + se, gb_h + ge);
            cp16(sB_lo + buf * PJ_TB + se, gb_l + ge);
        }
    };

    load_stage(0, 0);
    CP_COMMIT();

    const int NS = KDIM / 32;
    for (int s = 0; s < NS; s++) {
        if (s + 1 < NS) { load_stage(s + 1, (s + 1) & 1); CP_COMMIT(); CP_WAIT(1); }
        else            { CP_WAIT(0); }
        __syncthreads();

        const int buf = s & 1;
        const uint32_t* uAh = (const uint32_t*)(sA_hi + buf * PJ_TB);
        const uint32_t* uAl = (const uint32_t*)(sA_lo + buf * PJ_TB);
        const uint32_t* uBh = (const uint32_t*)(sB_hi + buf * PJ_TB);
        const uint32_t* uBl = (const uint32_t*)(sB_lo + buf * PJ_TB);

#pragma unroll
        for (int kk = 0; kk < 2; kk++) {
            const int colu = kk * 8 + ke;
            uint32_t ah[4][4], al[4][4];
#pragma unroll
            for (int mt = 0; mt < 4; mt++) {
                int r = wm * 64 + mt * 16 + g;
                int o0 = r * 20 + colu;
                ah[mt][0] = uAh[o0];            ah[mt][1] = uAh[o0 + 160];
                ah[mt][2] = uAh[o0 + 4];        ah[mt][3] = uAh[o0 + 164];
                al[mt][0] = uAl[o0];            al[mt][1] = uAl[o0 + 160];
                al[mt][2] = uAl[o0 + 4];        al[mt][3] = uAl[o0 + 164];
            }
            uint32_t bh[4][2], bl[4][2];
#pragma unroll
            for (int nt = 0; nt < 4; nt++) {
                int r = wn * 32 + nt * 8 + g;
                int o0 = r * 20 + colu;
                bh[nt][0] = uBh[o0];  bh[nt][1] = uBh[o0 + 4];
                bl[nt][0] = uBl[o0];  bl[nt][1] = uBl[o0 + 4];
            }
#pragma unroll
            for (int mt = 0; mt < 4; mt++)
#pragma unroll
                for (int nt = 0; nt < 4; nt++) {
                    mma_bf16(acc[mt][nt], ah[mt], bh[nt][0], bh[nt][1]);
                    mma_bf16(acc[mt][nt], ah[mt], bl[nt][0], bl[nt][1]);
                    mma_bf16(acc[mt][nt], al[mt], bh[nt][0], bh[nt][1]);
                }
        }
        __syncthreads();
    }

    // epilogue
#pragma unroll
    for (int mt = 0; mt < 4; mt++) {
#pragma unroll
        for (int nt = 0; nt < 4; nt++) {
            int r = m0 + wm * 64 + mt * 16 + g;
            int c = n0 + wn * 32 + nt * 8 + (lane & 3) * 2;
            float bx = bias[c], by = bias[c + 1];
            float v00 = acc[mt][nt][0] + bx, v01 = acc[mt][nt][1] + by;
            float v10 = acc[mt][nt][2] + bx, v11 = acc[mt][nt][3] + by;
            if (MODE == 0) {
                *(float2*)(outF + (size_t)r * DMODEL + c)       = make_float2(v00, v01);
                *(float2*)(outF + (size_t)(r + 8) * DMODEL + c) = make_float2(v10, v11);
            } else if (MODE == 1) {
                int b_ = r >> 11, hh = c >> 6, d = c & 63;
                int t0 = r & 2047;
                size_t d0 = (((size_t)(b_ * NHEAD + hh) * T_DIM + t0) * DKH) + d;
                size_t d1 = (((size_t)(b_ * NHEAD + hh) * T_DIM + t0 + 8) * DKH) + d;
                uint32_t hi, lo;
                split2(v00, v01, hi, lo);
                *(uint32_t*)(outHi + d0) = hi; *(uint32_t*)(outLo + d0) = lo;
                split2(v10, v11, hi, lo);
                *(uint32_t*)(outHi + d1) = hi; *(uint32_t*)(outLo + d1) = lo;
            } else {
                int b_ = r >> 11, hh = c >> 6, d = c & 63;
                int t0 = r & 2047;
                size_t base = ((size_t)(b_ * NHEAD + hh) * DKH + d) * T_DIM;
                __nv_bfloat16 h;
                h = __float2bfloat16_rn(v00); outHi[base + t0] = h;
                outLo[base + t0] = __float2bfloat16_rn(v00 - __bfloat162float(h));
                h = __float2bfloat16_rn(v01); outHi[base + T_DIM + t0] = h;
                outLo[base + T_DIM + t0] = __float2bfloat16_rn(v01 - __bfloat162float(h));
                h = __float2bfloat16_rn(v10); outHi[base + t0 + 8] = h;
                outLo[base + t0 + 8] = __float2bfloat16_rn(v10 - __bfloat162float(h));
                h = __float2bfloat16_rn(v11); outHi[base + T_DIM + t0 + 8] = h;
                outLo[base + T_DIM + t0 + 8] = __float2bfloat16_rn(v11 - __bfloat162float(h));
            }
        }
    }
}

// merged Q+K projection: blockIdx.z selects weight/bias/output set
__global__ __launch_bounds__(256) void proj_qk(
    const __nv_bfloat16* __restrict__ Ahi, const __nv_bfloat16* __restrict__ Alo,
    const __nv_bfloat16* __restrict__ Bh0, const __nv_bfloat16* __restrict__ Bl0,
    const float* __restrict__ bias0,
    __nv_bfloat16* __restrict__ oh0, __nv_bfloat16* __restrict__ ol0,
    const __nv_bfloat16* __restrict__ Bh1, const __nv_bfloat16* __restrict__ Bl1,
    const float* __restrict__ bias1,
    __nv_bfloat16* __restrict__ oh1, __nv_bfloat16* __restrict__ ol1)
{
    if (blockIdx.z == 0)
        proj_body<1>(Ahi, Alo, Bh0, Bl0, bias0, nullptr, oh0, ol0);
    else
        proj_body<1>(Ahi, Alo, Bh1, Bl1, bias1, nullptr, oh1, ol1);
}

__global__ __launch_bounds__(256) void proj_v(
    const __nv_bfloat16* __restrict__ Ahi, const __nv_bfloat16* __restrict__ Alo,
    const __nv_bfloat16* __restrict__ Bhi, const __nv_bfloat16* __restrict__ Blo,
    const float* __restrict__ bias,
    __nv_bfloat16* __restrict__ outHi, __nv_bfloat16* __restrict__ outLo)
{
    proj_body<2>(Ahi, Alo, Bhi, Blo, bias, nullptr, outHi, outLo);
}

__global__ __launch_bounds__(256) void proj_o(
    const __nv_bfloat16* __restrict__ Ahi, const __nv_bfloat16* __restrict__ Alo,
    const __nv_bfloat16* __restrict__ Bhi, const __nv_bfloat16* __restrict__ Blo,
    const float* __restrict__ bias, float* __restrict__ outF)
{
    proj_body<0>(Ahi, Alo, Bhi, Blo, bias, outF, nullptr, nullptr);
}

// ---------------- flash attention (bf16x3, mma.sync) — round-3 body ----------------
#define FL_KT   (64 * 72)
#define FL_SMEM (4 * 2 * FL_KT * 2)

__global__ __launch_bounds__(256) void flash_mma(
    const float* __restrict__ bias,
    const __nv_bfloat16* __restrict__ Qhi, const __nv_bfloat16* __restrict__ Qlo,
    const __nv_bfloat16* __restrict__ Khi, const __nv_bfloat16* __restrict__ Klo,
    const __nv_bfloat16* __restrict__ Vhi, const __nv_bfloat16* __restrict__ Vlo,
    __nv_bfloat16* __restrict__ Ohi, __nv_bfloat16* __restrict__ Olo)
{
    extern __shared__ __align__(16) unsigned char smem_raw[];
    __nv_bfloat16* sK_hi = (__nv_bfloat16*)smem_raw;
    __nv_bfloat16* sK_lo = sK_hi + 2 * FL_KT;
    __nv_bfloat16* sV_hi = sK_lo + 2 * FL_KT;
    __nv_bfloat16* sV_lo = sV_hi + 2 * FL_KT;

    const int tid = threadIdx.x;
    const int lane = tid & 31, wid = tid >> 5;
    const int q0 = blockIdx.x * 128;
    const int h  = blockIdx.y;
    const int b  = blockIdx.z;
    const size_t bh = (size_t)b * NHEAD + h;

    const __nv_bfloat16* qh = Qhi + bh * T_DIM * DKH;
    const __nv_bfloat16* ql = Qlo + bh * T_DIM * DKH;
    const __nv_bfloat16* kh = Khi + bh * T_DIM * DKH;
    const __nv_bfloat16* kl = Klo + bh * T_DIM * DKH;
    const __nv_bfloat16* vh = Vhi + bh * DKH * T_DIM;
    const __nv_bfloat16* vl = Vlo + bh * DKH * T_DIM;
    const float* bp = bias + (size_t)h * T_DIM * T_DIM;

    const int g  = lane >> 2;
    const int ke = (lane & 3) * 2;
    const int qr = q0 + wid * 16 + g;

    uint32_t qAh[4][4], qAl[4][4];
#pragma unroll
    for (int kt = 0; kt < 4; kt++) {
        size_t base = (size_t)qr * DKH + kt * 16 + ke;
        qAh[kt][0] = *(const uint32_t*)(qh + base);
        qAh[kt][1] = *(const uint32_t*)(qh + base + 8 * DKH);
        qAh[kt][2] = *(const uint32_t*)(qh + base + 8);
        qAh[kt][3] = *(const uint32_t*)(qh + base + 8 * DKH + 8);
        qAl[kt][0] = *(const uint32_t*)(ql + base);
        qAl[kt][1] = *(const uint32_t*)(ql + base + 8 * DKH);
        qAl[kt][2] = *(const uint32_t*)(ql + base + 8);
        qAl[kt][3] = *(const uint32_t*)(ql + base + 8 * DKH + 8);
    }

    float m0r = -1e30f, m1r = -1e30f, l0r = 0.0f, l1r = 0.0f;
    float o[8][4];
#pragma unroll
    for (int i = 0; i < 8; i++)
#pragma unroll
        for (int j = 0; j < 4; j++) o[i][j] = 0.0f;

    const int lrow = tid >> 3;
    const int lch  = (tid & 7) * 8;

    auto load_chunk = [&](int c, int buf) {
        int k0 = c * 64;
#pragma unroll
        for (int i = 0; i < 2; i++) {
            int r = lrow + i * 32;
            int se = r * 72 + lch;
            cp16(sK_hi + buf * FL_KT + se, kh + (size_t)(k0 + r) * DKH + lch);
            cp16(sK_lo + buf * FL_KT + se, kl + (size_t)(k0 + r) * DKH + lch);
            cp16(sV_hi + buf * FL_KT + se, vh + (size_t)r * T_DIM + k0 + lch);
            cp16(sV_lo + buf * FL_KT + se, vl + (size_t)r * T_DIM + k0 + lch);
        }
    };

    load_chunk(0, 0);
    CP_COMMIT();

    const int NCH = T_DIM / 64;
    for (int c = 0; c < NCH; c++) {
        if (c + 1 < NCH) { load_chunk(c + 1, (c + 1) & 1); CP_COMMIT(); CP_WAIT(1); }
        else             { CP_WAIT(0); }
        __syncthreads();

        const int buf = c & 1;
        const int k0 = c * 64;
        const uint32_t* uKh = (const uint32_t*)(sK_hi + buf * FL_KT);
        const uint32_t* uKl = (const uint32_t*)(sK_lo + buf * FL_KT);
        const uint32_t* uVh = (const uint32_t*)(sV_hi + buf * FL_KT);
        const uint32_t* uVl = (const uint32_t*)(sV_lo + buf * FL_KT);

        float s[8][4];
#pragma unroll
        for (int i = 0; i < 8; i++)
#pragma unroll
            for (int j = 0; j < 4; j++) s[i][j] = 0.0f;

#pragma unroll
        for (int kt = 0; kt < 4; kt++) {
            const int colu = kt * 8 + (lane & 3);
#pragma unroll
            for (int nt = 0; nt < 8; nt++) {
                int o0 = (nt * 8 + g) * 36 + colu;
                uint32_t bh0 = uKh[o0], bh1 = uKh[o0 + 4];
                uint32_t bl0 = uKl[o0], bl1 = uKl[o0 + 4];
                mma_bf16(s[nt], qAh[kt], bh0, bh1);
                mma_bf16(s[nt], qAh[kt], bl0, bl1);
                mma_bf16(s[nt], qAl[kt], bh0, bh1);
            }
        }

#pragma unroll
        for (int nt = 0; nt < 8; nt++) {
            const float* bb = bp + (size_t)qr * T_DIM + k0 + nt * 8 + ke;
            float2 b0 = *(const float2*)bb;
            float2 b1 = *(const float2*)(bb + 8 * T_DIM);
            s[nt][0] = fmaf(s[nt][0], 0.125f, b0.x);
            s[nt][1] = fmaf(s[nt][1], 0.125f, b0.y);
            s[nt][2] = fmaf(s[nt][2], 0.125f, b1.x);
            s[nt][3] = fmaf(s[nt][3], 0.125f, b1.y);
        }

        float t0 = -1e30f, t1 = -1e30f;
#pragma unroll
        for (int nt = 0; nt < 8; nt++) {
            t0 = fmaxf(t0, fmaxf(s[nt][0], s[nt][1]));
            t1 = fmaxf(t1, fmaxf(s[nt][2], s[nt][3]));
        }
        t0 = fmaxf(t0, __shfl_xor_sync(0xffffffffu, t0, 1));
        t0 = fmaxf(t0, __shfl_xor_sync(0xffffffffu, t0, 2));
        t1 = fmaxf(t1, __shfl_xor_sync(0xffffffffu, t1, 1));
        t1 = fmaxf(t1, __shfl_xor_sync(0xffffffffu, t1, 2));
        float nm0 = fmaxf(m0r, t0), nm1 = fmaxf(m1r, t1);
        float al0 = fexp(m0r - nm0), al1 = fexp(m1r - nm1);
        m0r = nm0; m1r = nm1;

        float sum0 = 0.0f, sum1 = 0.0f;
#pragma unroll
        for (int nt = 0; nt < 8; nt++) {
            s[nt][0] = fexp(s[nt][0] - nm0); sum0 += s[nt][0];
            s[nt][1] = fexp(s[nt][1] - nm0); sum0 += s[nt][1];
            s[nt][2] = fexp(s[nt][2] - nm1); sum1 += s[nt][2];
            s[nt][3] = fexp(s[nt][3] - nm1); sum1 += s[nt][3];
        }
        sum0 += __shfl_xor_sync(0xffffffffu, sum0, 1);
        sum0 += __shfl_xor_sync(0xffffffffu, sum0, 2);
        sum1 += __shfl_xor_sync(0xffffffffu, sum1, 1);
        sum1 += __shfl_xor_sync(0xffffffffu, sum1, 2);
        l0r = l0r * al0 + sum0;
        l1r = l1r * al1 + sum1;

#pragma unroll
        for (int nt = 0; nt < 8; nt++) {
            o[nt][0] *= al0; o[nt][1] *= al0;
            o[nt][2] *= al1; o[nt][3] *= al1;
        }

#pragma unroll
        for (int kt = 0; kt < 4; kt++) {
            const int e = 2 * kt;
            uint32_t pAh[4], pAl[4];
            split2(s[e][0],     s[e][1],     pAh[0], pAl[0]);
            split2(s[e][2],     s[e][3],     pAh[1], pAl[1]);
            split2(s[e + 1][0], s[e + 1][1], pAh[2], pAl[2]);
            split2(s[e + 1][2], s[e + 1][3], pAh[3], pAl[3]);
            const int colu = kt * 8 + (lane & 3);
#pragma unroll
            for (int nt = 0; nt < 8; nt++) {
                int o0 = (nt * 8 + g) * 36 + colu;
                uint32_t vh0 = uVh[o0], vh1 = uVh[o0 + 4];
                uint32_t vl0 = uVl[o0], vl1 = uVl[o0 + 4];
                mma_bf16(o[nt], pAh, vh0, vh1);
                mma_bf16(o[nt], pAh, vl0, vl1);
                mma_bf16(o[nt], pAl, vh0, vh1);
            }
        }
        __syncthreads();
    }

    float i0 = __fdividef(1.0f, l0r), i1 = __fdividef(1.0f, l1r);
#pragma unroll
    for (int nt = 0; nt < 8; nt++) {
        float v00 = o[nt][0] * i0, v01 = o[nt][1] * i0;
        float v10 = o[nt][2] * i1, v11 = o[nt][3] * i1;
        int d = h * DKH + nt * 8 + ke;
        size_t d0 = ((size_t)(b * T_DIM + qr)) * DMODEL + d;
        size_t d1 = ((size_t)(b * T_DIM + qr + 8)) * DMODEL + d;
        uint32_t hi, lo;
        split2(v00, v01, hi, lo);
        *(uint32_t*)(Ohi + d0) = hi; *(uint32_t*)(Olo + d0) = lo;
        split2(v10, v11, hi, lo);
        *(uint32_t*)(Ohi + d1) = hi; *(uint32_t*)(Olo + d1) = lo;
    }
}

// ---------------- launch ----------------
extern "C" void kernel_launch(void* const* d_in, const int* in_sizes, int n_in,
                              void* d_out, int out_size)
{
    const float* x    = (const float*)d_in[0];
    const float* bias = (const float*)d_in[1];
    const float* Wq   = (const float*)d_in[2];
    const float* bq   = (const float*)d_in[3];
    const float* Wk   = (const float*)d_in[4];
    const float* bk   = (const float*)d_in[5];
    const float* Wv   = (const float*)d_in[6];
    const float* bv   = (const float*)d_in[7];
    const float* Wo   = (const float*)d_in[8];
    const float* bo   = (const float*)d_in[9];
    float* out = (float*)d_out;

    __nv_bfloat16 *xhi, *xlo, *whi, *wlo, *qhi, *qlo, *khi, *klo, *vhi, *vlo, *ahi, *alo;
    cudaGetSymbolAddress((void**)&xhi, g_xhi); cudaGetSymbolAddress((void**)&xlo, g_xlo);
    cudaGetSymbolAddress((void**)&whi, g_whi); cudaGetSymbolAddress((void**)&wlo, g_wlo);
    cudaGetSymbolAddress((void**)&qhi, g_qhi); cudaGetSymbolAddress((void**)&qlo, g_qlo);
    cudaGetSymbolAddress((void**)&khi, g_khi); cudaGetSymbolAddress((void**)&klo, g_klo);
    cudaGetSymbolAddress((void**)&vhi, g_vhi); cudaGetSymbolAddress((void**)&vlo, g_vlo);
    cudaGetSymbolAddress((void**)&ahi, g_ahi); cudaGetSymbolAddress((void**)&alo, g_alo);

    cudaFuncSetAttribute(proj_qk,  cudaFuncAttributeMaxDynamicSharedMemorySize, PJ_SMEM);
    cudaFuncSetAttribute(proj_v,   cudaFuncAttributeMaxDynamicSharedMemorySize, PJ_SMEM);
    cudaFuncSetAttribute(proj_o,   cudaFuncAttributeMaxDynamicSharedMemorySize, PJ_SMEM);
    cudaFuncSetAttribute(flash_mma, cudaFuncAttributeMaxDynamicSharedMemorySize, FL_SMEM);

    const int WN = DMODEL * DMODEL;  // 1M

    // [0] fused splits (x + 4 weights)
    fused_split_kernel<<<dim3(M_DIM * DMODEL / 1024, 5), 256>>>(
        x, Wq, Wk, Wv, Wo, xhi, xlo, whi, wlo);

    dim3 gg(DMODEL / 128, M_DIM / 128);  // (8, 32)

    // [1] Q + K projections in one launch (z = 0/1)
    proj_qk<<<dim3(gg.x, gg.y, 2), 256, PJ_SMEM>>>(
        xhi, xlo,
        whi + 0 * WN, wlo + 0 * WN, bq, qhi, qlo,
        whi + 1 * WN, wlo + 1 * WN, bk, khi, klo);

    // [2] V projection (transposed output)
    proj_v<<<gg, 256, PJ_SMEM>>>(xhi, xlo, whi + 2 * WN, wlo + 2 * WN, bv, vhi, vlo);

    // [3] flash attention  (position 3 — lands on the ncu capture index)
    flash_mma<<<dim3(T_DIM / 128, NHEAD, B_DIM), 256, FL_SMEM>>>(
        bias, qhi, qlo, khi, klo, vhi, vlo, ahi, alo);

    // [4] output projection
    proj_o<<<gg, 256, PJ_SMEM>>>(ahi, alo, whi + 3 * WN, wlo + 3 * WN, bo, out);
}

// round 13
// speedup vs baseline: 1.0386x; 1.0386x over previous
#include <cuda_runtime.h>
#include <cuda_fp16.h>
#include <cstdint>

// ---------------- problem constants ----------------
#define B_DIM   2
#define T_DIM   2048
#define DMODEL  1024
#define NHEAD   16
#define DKH     64
#define M_DIM   (B_DIM * T_DIM)      // 4096
#define KDIM    DMODEL

// ---------------- scratch (device globals, no allocs) ----------------
// fp16 scheme: A-operands split hi/lo, B-operands hi only.
__device__ __half g_xhi[M_DIM * DMODEL], g_xlo[M_DIM * DMODEL];
__device__ __half g_whi[4 * DMODEL * DMODEL];                       // weights: hi only
__device__ __half g_qhi[M_DIM * DMODEL], g_qlo[M_DIM * DMODEL];     // Q: [B,H,T,dk] hi/lo
__device__ __half g_khi[M_DIM * DMODEL];                            // K: [B,H,T,dk] hi only
__device__ __half g_vhi[M_DIM * DMODEL];                            // V: [B,H,dk,T] hi only
__device__ __half g_ahi[M_DIM * DMODEL], g_alo[M_DIM * DMODEL];     // attn out: [B,T,D] hi/lo

// ---------------- helpers ----------------
__device__ __forceinline__ unsigned short h2u(__half h) {
    return *reinterpret_cast<unsigned short*>(&h);
}

// split two floats into packed fp16 hi and fp16 lo (residual)
__device__ __forceinline__ void splith2(float a, float b, uint32_t& hi, uint32_t& lo) {
    __half ha = __float2half_rn(a), hb = __float2half_rn(b);
    float ra = a - __half2float(ha), rb = b - __half2float(hb);
    __half la = __float2half_rn(ra), lb = __float2half_rn(rb);
    hi = ((uint32_t)h2u(hb) << 16) | (uint32_t)h2u(ha);
    lo = ((uint32_t)h2u(lb) << 16) | (uint32_t)h2u(la);
}

__device__ __forceinline__ uint32_t packh2(float a, float b) {
    __half ha = __float2half_rn(a), hb = __float2half_rn(b);
    return ((uint32_t)h2u(hb) << 16) | (uint32_t)h2u(ha);
}

__device__ __forceinline__ float fexp(float x) {
    float y = x * 1.4426950408889634f;
    y = fmaxf(y, -120.0f);
    float n = floorf(y);
    float f = y - n;
    float p = 1.5403530393381606e-4f;
    p = fmaf(p, f, 1.3333558146428443e-3f);
    p = fmaf(p, f, 9.6181291076284771e-3f);
    p = fmaf(p, f, 5.5504108664821580e-2f);
    p = fmaf(p, f, 2.4022650695910071e-1f);
    p = fmaf(p, f, 6.9314718055994531e-1f);
    p = fmaf(p, f, 1.0f);
    float r = __int_as_float(((int)n + 127) << 23);
    return p * r;
}

__device__ __forceinline__ void mma_f16(float* c, const uint32_t* a, uint32_t b0, uint32_t b1) {
    asm volatile(
        "mma.sync.aligned.m16n8k16.row.col.f32.f16.f16.f32 "
        "{%0,%1,%2,%3}, {%4,%5,%6,%7}, {%8,%9}, {%0,%1,%2,%3};"
        : "+f"(c[0]), "+f"(c[1]), "+f"(c[2]), "+f"(c[3])
        : "r"(a[0]), "r"(a[1]), "r"(a[2]), "r"(a[3]), "r"(b0), "r"(b1));
}

__device__ __forceinline__ void cp16(void* dst, const void* src) {
    uint32_t d = (uint32_t)__cvta_generic_to_shared(dst);
    asm volatile("cp.async.cg.shared.global [%0], [%1], 16;" :: "r"(d), "l"(src));
}
#define CP_COMMIT()  asm volatile("cp.async.commit_group;")
#define CP_WAIT(N)   asm volatile("cp.async.wait_group %0;" :: "n"(N))

// ---------------- fused fp16 split kernel (x hi/lo + 4 weights hi-only) ----------------
__global__ void fused_split_kernel(
    const float* __restrict__ x,
    const float* __restrict__ Wq, const float* __restrict__ Wk,
    const float* __restrict__ Wv, const float* __restrict__ Wo,
    __half* __restrict__ xhi, __half* __restrict__ xlo,
    __half* __restrict__ whi)
{
    const int WN = DMODEL * DMODEL;
    const int y = blockIdx.y;
    int i = (blockIdx.x * blockDim.x + threadIdx.x) * 4;
    if (y == 0) {
        float4 v = *(const float4*)(x + i);
        uint32_t h0, l0, h1, l1;
        splith2(v.x, v.y, h0, l0);
        splith2(v.z, v.w, h1, l1);
        *(uint2*)(xhi + i) = make_uint2(h0, h1);
        *(uint2*)(xlo + i) = make_uint2(l0, l1);
    } else if (i < WN) {
        const float* ws[4] = {Wq, Wk, Wv, Wo};
        const float* src = ws[y - 1];
        __half* hi = whi + (size_t)(y - 1) * WN;
        float4 v = *(const float4*)(src + i);
        *(uint2*)(hi + i) = make_uint2(packh2(v.x, v.y), packh2(v.z, v.w));
    }
}

// ---------------- projection GEMM body (fp16 A-split, mma.sync) ----------------
// C[M,N] = A[M,K] * W[N,K]^T + bias, tile 128x128, BK=32, 256 thr, warp tile 64x32.
// MODE 0: fp32 flat [M,D]; MODE 1: hi/lo [B,H,T,dk]; MODE 2: hi only [B,H,dk,T]; MODE 3: hi only [B,H,T,dk]
#define PJ_TB   (128 * 40)
#define PJ_SMEM (3 * 2 * PJ_TB * 2)

template <int MODE>
__device__ __forceinline__ void proj_body(
    const __half* __restrict__ Ahi, const __half* __restrict__ Alo,
    const __half* __restrict__ Bhi,
    const float* __restrict__ bias,
    float* __restrict__ outF,
    __half* __restrict__ outHi, __half* __restrict__ outLo)
{
    extern __shared__ __align__(16) unsigned char smem_raw[];
    __half* sA_hi = (__half*)smem_raw;
    __half* sA_lo = sA_hi + 2 * PJ_TB;
    __half* sB_hi = sA_lo + 2 * PJ_TB;

    const int tid = threadIdx.x;
    const int lane = tid & 31, wid = tid >> 5;
    const int wm = wid >> 2, wn = wid & 3;      // 2 x 4 warps
    const int m0 = blockIdx.y * 128, n0 = blockIdx.x * 128;
    const int g = lane >> 2;
    const int ke = (lane & 3);                  // u32 column unit within k16

    const int lrow = tid >> 2;                  // 0..63
    const int lch  = (tid & 3) * 8;             // elem offset of 16B chunk

    float acc[4][4][4];
#pragma unroll
    for (int a = 0; a < 4; a++)
#pragma unroll
        for (int b = 0; b < 4; b++)
#pragma unroll
            for (int c = 0; c < 4; c++) acc[a][b][c] = 0.0f;

    auto load_stage = [&](int s, int buf) {
        int k0 = s * 32;
        const __half* ga_h = Ahi + (size_t)m0 * KDIM + k0;
        const __half* ga_l = Alo + (size_t)m0 * KDIM + k0;
        const __half* gb_h = Bhi + (size_t)n0 * KDIM + k0;
#pragma unroll
        for (int i = 0; i < 2; i++) {
            int r = lrow + i * 64;
            int se = r * 40 + lch;
            size_t ge = (size_t)r * KDIM + lch;
            cp16(sA_hi + buf * PJ_TB + se, ga_h + ge);
            cp16(sA_lo + buf * PJ_TB + se, ga_l + ge);
            cp16(sB_hi + buf * PJ_TB + se, gb_h + ge);
        }
    };

    load_stage(0, 0);
    CP_COMMIT();

    const int NS = KDIM / 32;
    for (int s = 0; s < NS; s++) {
        if (s + 1 < NS) { load_stage(s + 1, (s + 1) & 1); CP_COMMIT(); CP_WAIT(1); }
        else            { CP_WAIT(0); }
        __syncthreads();

        const int buf = s & 1;
        const uint32_t* uAh = (const uint32_t*)(sA_hi + buf * PJ_TB);
        const uint32_t* uAl = (const uint32_t*)(sA_lo + buf * PJ_TB);
        const uint32_t* uBh = (const uint32_t*)(sB_hi + buf * PJ_TB);

#pragma unroll
        for (int kk = 0; kk < 2; kk++) {
            const int colu = kk * 8 + ke;
            uint32_t ah[4][4], al[4][4];
#pragma unroll
            for (int mt = 0; mt < 4; mt++) {
                int r = wm * 64 + mt * 16 + g;
                int o0 = r * 20 + colu;
                ah[mt][0] = uAh[o0];            ah[mt][1] = uAh[o0 + 160];
                ah[mt][2] = uAh[o0 + 4];        ah[mt][3] = uAh[o0 + 164];
                al[mt][0] = uAl[o0];            al[mt][1] = uAl[o0 + 160];
                al[mt][2] = uAl[o0 + 4];        al[mt][3] = uAl[o0 + 164];
            }
            uint32_t bh[4][2];
#pragma unroll
            for (int nt = 0; nt < 4; nt++) {
                int r = wn * 32 + nt * 8 + g;
                int o0 = r * 20 + colu;
                bh[nt][0] = uBh[o0];  bh[nt][1] = uBh[o0 + 4];
            }
#pragma unroll
            for (int mt = 0; mt < 4; mt++)
#pragma unroll
                for (int nt = 0; nt < 4; nt++) {
                    mma_f16(acc[mt][nt], ah[mt], bh[nt][0], bh[nt][1]);
                    mma_f16(acc[mt][nt], al[mt], bh[nt][0], bh[nt][1]);
                }
        }
        __syncthreads();
    }

    // epilogue
#pragma unroll
    for (int mt = 0; mt < 4; mt++) {
#pragma unroll
        for (int nt = 0; nt < 4; nt++) {
            int r = m0 + wm * 64 + mt * 16 + g;
            int c = n0 + wn * 32 + nt * 8 + (lane & 3) * 2;
            float bx = bias[c], by = bias[c + 1];
            float v00 = acc[mt][nt][0] + bx, v01 = acc[mt][nt][1] + by;
            float v10 = acc[mt][nt][2] + bx, v11 = acc[mt][nt][3] + by;
            if (MODE == 0) {
                *(float2*)(outF + (size_t)r * DMODEL + c)       = make_float2(v00, v01);
                *(float2*)(outF + (size_t)(r + 8) * DMODEL + c) = make_float2(v10, v11);
            } else if (MODE == 1) {
                int b_ = r >> 11, hh = c >> 6, d = c & 63;
                int t0 = r & 2047;
                size_t d0 = (((size_t)(b_ * NHEAD + hh) * T_DIM + t0) * DKH) + d;
                size_t d1 = (((size_t)(b_ * NHEAD + hh) * T_DIM + t0 + 8) * DKH) + d;
                uint32_t hi, lo;
                splith2(v00, v01, hi, lo);
                *(uint32_t*)(outHi + d0) = hi; *(uint32_t*)(outLo + d0) = lo;
                splith2(v10, v11, hi, lo);
                *(uint32_t*)(outHi + d1) = hi; *(uint32_t*)(outLo + d1) = lo;
            } else if (MODE == 3) {
                int b_ = r >> 11, hh = c >> 6, d = c & 63;
                int t0 = r & 2047;
                size_t d0 = (((size_t)(b_ * NHEAD + hh) * T_DIM + t0) * DKH) + d;
                size_t d1 = (((size_t)(b_ * NHEAD + hh) * T_DIM + t0 + 8) * DKH) + d;
                *(uint32_t*)(outHi + d0) = packh2(v00, v01);
                *(uint32_t*)(outHi + d1) = packh2(v10, v11);
            } else {
                // MODE 2: V hi-only into [B,H,dk,T]
                int b_ = r >> 11, hh = c >> 6, d = c & 63;
                int t0 = r & 2047;
                size_t base = ((size_t)(b_ * NHEAD + hh) * DKH + d) * T_DIM;
                outHi[base + t0]             = __float2half_rn(v00);
                outHi[base + T_DIM + t0]     = __float2half_rn(v01);
                outHi[base + t0 + 8]         = __float2half_rn(v10);
                outHi[base + T_DIM + t0 + 8] = __float2half_rn(v11);
            }
        }
    }
}

// merged Q+K projection: blockIdx.z selects weight/bias/output set
__global__ __launch_bounds__(256) void proj_qk(
    const __half* __restrict__ Ahi, const __half* __restrict__ Alo,
    const __half* __restrict__ Bh0, const float* __restrict__ bias0,
    __half* __restrict__ oh0, __half* __restrict__ ol0,
    const __half* __restrict__ Bh1, const float* __restrict__ bias1,
    __half* __restrict__ oh1)
{
    if (blockIdx.z == 0)
        proj_body<1>(Ahi, Alo, Bh0, bias0, nullptr, oh0, ol0);
    else
        proj_body<3>(Ahi, Alo, Bh1, bias1, nullptr, oh1, nullptr);
}

__global__ __launch_bounds__(256) void proj_v(
    const __half* __restrict__ Ahi, const __half* __restrict__ Alo,
    const __half* __restrict__ Bhi, const float* __restrict__ bias,
    __half* __restrict__ outHi)
{
    proj_body<2>(Ahi, Alo, Bhi, bias, nullptr, outHi, nullptr);
}

__global__ __launch_bounds__(256) void proj_o(
    const __half* __restrict__ Ahi, const __half* __restrict__ Alo,
    const __half* __restrict__ Bhi, const float* __restrict__ bias,
    float* __restrict__ outF)
{
    proj_body<0>(Ahi, Alo, Bhi, bias, outF, nullptr, nullptr);
}

// ---------------- flash attention (fp16 A-split, mma.sync) ----------------
#define FL_KT   (64 * 72)
#define FL_SMEM (2 * 2 * FL_KT * 2)

__global__ __launch_bounds__(256) void flash_mma(
    const float* __restrict__ bias,
    const __half* __restrict__ Qhi, const __half* __restrict__ Qlo,
    const __half* __restrict__ Khi, const __half* __restrict__ Vhi,
    __half* __restrict__ Ohi, __half* __restrict__ Olo)
{
    extern __shared__ __align__(16) unsigned char smem_raw[];
    __half* sK_hi = (__half*)smem_raw;
    __half* sV_hi = sK_hi + 2 * FL_KT;

    const int tid = threadIdx.x;
    const int lane = tid & 31, wid = tid >> 5;
    const int q0 = blockIdx.x * 128;
    const int h  = blockIdx.y;
    const int b  = blockIdx.z;
    const size_t bh = (size_t)b * NHEAD + h;

    const __half* qh = Qhi + bh * T_DIM * DKH;
    const __half* ql = Qlo + bh * T_DIM * DKH;
    const __half* kh = Khi + bh * T_DIM * DKH;
    const __half* vh = Vhi + bh * DKH * T_DIM;
    const float* bp = bias + (size_t)h * T_DIM * T_DIM;

    const int g  = lane >> 2;
    const int ke = (lane & 3) * 2;
    const int qr = q0 + wid * 16 + g;

    uint32_t qAh[4][4], qAl[4][4];
#pragma unroll
    for (int kt = 0; kt < 4; kt++) {
        size_t base = (size_t)qr * DKH + kt * 16 + ke;
        qAh[kt][0] = *(const uint32_t*)(qh + base);
        qAh[kt][1] = *(const uint32_t*)(qh + base + 8 * DKH);
        qAh[kt][2] = *(const uint32_t*)(qh + base + 8);
        qAh[kt][3] = *(const uint32_t*)(qh + base + 8 * DKH + 8);
        qAl[kt][0] = *(const uint32_t*)(ql + base);
        qAl[kt][1] = *(const uint32_t*)(ql + base + 8 * DKH);
        qAl[kt][2] = *(const uint32_t*)(ql + base + 8);
        qAl[kt][3] = *(const uint32_t*)(ql + base + 8 * DKH + 8);
    }

    float m0r = -1e30f, m1r = -1e30f, l0r = 0.0f, l1r = 0.0f;
    float o[8][4];
#pragma unroll
    for (int i = 0; i < 8; i++)
#pragma unroll
        for (int j = 0; j < 4; j++) o[i][j] = 0.0f;

    const int lrow = tid >> 3;          // 0..31
    const int lch  = (tid & 7) * 8;

    auto load_chunk = [&](int c, int buf) {
        int k0 = c * 64;
#pragma unroll
        for (int i = 0; i < 2; i++) {
            int r = lrow + i * 32;
            int se = r * 72 + lch;
            cp16(sK_hi + buf * FL_KT + se, kh + (size_t)(k0 + r) * DKH + lch);
            cp16(sV_hi + buf * FL_KT + se, vh + (size_t)r * T_DIM + k0 + lch);
        }
    };

    load_chunk(0, 0);
    CP_COMMIT();

    const int NCH = T_DIM / 64;
    for (int c = 0; c < NCH; c++) {
        if (c + 1 < NCH) { load_chunk(c + 1, (c + 1) & 1); CP_COMMIT(); CP_WAIT(1); }
        else             { CP_WAIT(0); }
        __syncthreads();

        const int buf = c & 1;
        const int k0 = c * 64;
        const uint32_t* uKh = (const uint32_t*)(sK_hi + buf * FL_KT);
        const uint32_t* uVh = (const uint32_t*)(sV_hi + buf * FL_KT);

        // ---- S = Q K^T (fp16 A-split, 2 MMAs) ----
        float s[8][4];
#pragma unroll
        for (int i = 0; i < 8; i++)
#pragma unroll
            for (int j = 0; j < 4; j++) s[i][j] = 0.0f;

#pragma unroll
        for (int kt = 0; kt < 4; kt++) {
            const int colu = kt * 8 + (lane & 3);
#pragma unroll
            for (int nt = 0; nt < 8; nt++) {
                int o0 = (nt * 8 + g) * 36 + colu;
                uint32_t bh0 = uKh[o0], bh1 = uKh[o0 + 4];
                mma_f16(s[nt], qAh[kt], bh0, bh1);
                mma_f16(s[nt], qAl[kt], bh0, bh1);
            }
        }

        // ---- scale + bias ----
#pragma unroll
        for (int nt = 0; nt < 8; nt++) {
            const float* bb = bp + (size_t)qr * T_DIM + k0 + nt * 8 + ke;
            float2 b0 = *(const float2*)bb;
            float2 b1 = *(const float2*)(bb + 8 * T_DIM);
            s[nt][0] = fmaf(s[nt][0], 0.125f, b0.x);
            s[nt][1] = fmaf(s[nt][1], 0.125f, b0.y);
            s[nt][2] = fmaf(s[nt][2], 0.125f, b1.x);
            s[nt][3] = fmaf(s[nt][3], 0.125f, b1.y);
        }

        // ---- online softmax (quad shfl reduction) ----
        float t0 = -1e30f, t1 = -1e30f;
#pragma unroll
        for (int nt = 0; nt < 8; nt++) {
            t0 = fmaxf(t0, fmaxf(s[nt][0], s[nt][1]));
            t1 = fmaxf(t1, fmaxf(s[nt][2], s[nt][3]));
        }
        t0 = fmaxf(t0, __shfl_xor_sync(0xffffffffu, t0, 1));
        t0 = fmaxf(t0, __shfl_xor_sync(0xffffffffu, t0, 2));
        t1 = fmaxf(t1, __shfl_xor_sync(0xffffffffu, t1, 1));
        t1 = fmaxf(t1, __shfl_xor_sync(0xffffffffu, t1, 2));
        float nm0 = fmaxf(m0r, t0), nm1 = fmaxf(m1r, t1);
        float al0 = fexp(m0r - nm0), al1 = fexp(m1r - nm1);
        m0r = nm0; m1r = nm1;

        float sum0 = 0.0f, sum1 = 0.0f;
#pragma unroll
        for (int nt = 0; nt < 8; nt++) {
            s[nt][0] = fexp(s[nt][0] - nm0); sum0 += s[nt][0];
            s[nt][1] = fexp(s[nt][1] - nm0); sum0 += s[nt][1];
            s[nt][2] = fexp(s[nt][2] - nm1); sum1 += s[nt][2];
            s[nt][3] = fexp(s[nt][3] - nm1); sum1 += s[nt][3];
        }
        sum0 += __shfl_xor_sync(0xffffffffu, sum0, 1);
        sum0 += __shfl_xor_sync(0xffffffffu, sum0, 2);
        sum1 += __shfl_xor_sync(0xffffffffu, sum1, 1);
        sum1 += __shfl_xor_sync(0xffffffffu, sum1, 2);
        l0r = l0r * al0 + sum0;
        l1r = l1r * al1 + sum1;

#pragma unroll
        for (int nt = 0; nt < 8; nt++) {
            o[nt][0] *= al0; o[nt][1] *= al0;
            o[nt][2] *= al1; o[nt][3] *= al1;
        }

        // ---- O += P V (fp16 P-split, 2 MMAs) ----
#pragma unroll
        for (int kt = 0; kt < 4; kt++) {
            const int e = 2 * kt;
            uint32_t pAh[4], pAl[4];
            splith2(s[e][0],     s[e][1],     pAh[0], pAl[0]);
            splith2(s[e][2],     s[e][3],     pAh[1], pAl[1]);
            splith2(s[e + 1][0], s[e + 1][1], pAh[2], pAl[2]);
            splith2(s[e + 1][2], s[e + 1][3], pAh[3], pAl[3]);
            const int colu = kt * 8 + (lane & 3);
#pragma unroll
            for (int nt = 0; nt < 8; nt++) {
                int o0 = (nt * 8 + g) * 36 + colu;
                uint32_t vh0 = uVh[o0], vh1 = uVh[o0 + 4];
                mma_f16(o[nt], pAh, vh0, vh1);
                mma_f16(o[nt], pAl, vh0, vh1);
            }
        }
        __syncthreads();
    }

    // ---- epilogue: O /= l, write fp16 hi/lo into [B,T,D] ----
    float i0 = __fdividef(1.0f, l0r), i1 = __fdividef(1.0f, l1r);
#pragma unroll
    for (int nt = 0; nt < 8; nt++) {
        float v00 = o[nt][0] * i0, v01 = o[nt][1] * i0;
        float v10 = o[nt][2] * i1, v11 = o[nt][3] * i1;
        int d = h * DKH + nt * 8 + ke;
        size_t d0 = ((size_t)(b * T_DIM + qr)) * DMODEL + d;
        size_t d1 = ((size_t)(b * T_DIM + qr + 8)) * DMODEL + d;
        uint32_t hi, lo;
        splith2(v00, v01, hi, lo);
        *(uint32_t*)(Ohi + d0) = hi; *(uint32_t*)(Olo + d0) = lo;
        splith2(v10, v11, hi, lo);
        *(uint32_t*)(Ohi + d1) = hi; *(uint32_t*)(Olo + d1) = lo;
    }
}

// ---------------- launch ----------------
extern "C" void kernel_launch(void* const* d_in, const int* in_sizes, int n_in,
                              void* d_out, int out_size)
{
    const float* x    = (const float*)d_in[0];
    const float* bias = (const float*)d_in[1];
    const float* Wq   = (const float*)d_in[2];
    const float* bq   = (const float*)d_in[3];
    const float* Wk   = (const float*)d_in[4];
    const float* bk   = (const float*)d_in[5];
    const float* Wv   = (const float*)d_in[6];
    const float* bv   = (const float*)d_in[7];
    const float* Wo   = (const float*)d_in[8];
    const float* bo   = (const float*)d_in[9];
    float* out = (float*)d_out;

    __half *xhi, *xlo, *whi, *qhi, *qlo, *khi, *vhi, *ahi, *alo;
    cudaGetSymbolAddress((void**)&xhi, g_xhi); cudaGetSymbolAddress((void**)&xlo, g_xlo);
    cudaGetSymbolAddress((void**)&whi, g_whi);
    cudaGetSymbolAddress((void**)&qhi, g_qhi); cudaGetSymbolAddress((void**)&qlo, g_qlo);
    cudaGetSymbolAddress((void**)&khi, g_khi);
    cudaGetSymbolAddress((void**)&vhi, g_vhi);
    cudaGetSymbolAddress((void**)&ahi, g_ahi); cudaGetSymbolAddress((void**)&alo, g_alo);

    cudaFuncSetAttribute(proj_qk,   cudaFuncAttributeMaxDynamicSharedMemorySize, PJ_SMEM);
    cudaFuncSetAttribute(proj_v,    cudaFuncAttributeMaxDynamicSharedMemorySize, PJ_SMEM);
    cudaFuncSetAttribute(proj_o,    cudaFuncAttributeMaxDynamicSharedMemorySize, PJ_SMEM);
    cudaFuncSetAttribute(flash_mma, cudaFuncAttributeMaxDynamicSharedMemorySize, FL_SMEM);

    const int WN = DMODEL * DMODEL;  // 1M

    // [0] fused splits (x hi/lo + 4 weights hi-only)
    fused_split_kernel<<<dim3(M_DIM * DMODEL / 1024, 5), 256>>>(
        x, Wq, Wk, Wv, Wo, xhi, xlo, whi);

    dim3 gg(DMODEL / 128, M_DIM / 128);  // (8, 32)

    // [1] Q + K projections in one launch (z = 0/1)
    proj_qk<<<dim3(gg.x, gg.y, 2), 256, PJ_SMEM>>>(
        xhi, xlo,
        whi + 0 * WN, bq, qhi, qlo,
        whi + 1 * WN, bk, khi);

    // [2] V projection (transposed, hi only)
    proj_v<<<gg, 256, PJ_SMEM>>>(xhi, xlo, whi + 2 * WN, bv, vhi);

    // [3] flash attention (position 3 — ncu capture index)
    flash_mma<<<dim3(T_DIM / 128, NHEAD, B_DIM), 256, FL_SMEM>>>(
        bias, qhi, qlo, khi, vhi, ahi, alo);

    // [4] output projection
    proj_o<<<gg, 256, PJ_SMEM>>>(ahi, alo, whi + 3 * WN, bo, out);
}